// round 16
// baseline (speedup 1.0000x reference)
#include <cuda_runtime.h>
#include <math.h>

#define S_LEN 60
#define D_IN  256
#define NHEAD 16
#define SC_STRIDE 68
#define V_FLOATS (S_LEN * D_IN)          // 15360
#define V_BYTES  (V_FLOATS * 4)          // 61440
#define GRID_P 148                       // persistent: 1 CTA per SM

typedef unsigned long long u64;

__device__ __align__(16) float g_weff[NHEAD * D_IN];

__device__ __forceinline__ u64 fma2(u64 a, u64 b, u64 c) {
    u64 d;
    asm("fma.rn.f32x2 %0, %1, %2, %3;" : "=l"(d) : "l"(a), "l"(b), "l"(c));
    return d;
}
__device__ __forceinline__ u64 mul2(u64 a, u64 b) {
    u64 d;
    asm("mul.rn.f32x2 %0, %1, %2;" : "=l"(d) : "l"(a), "l"(b));
    return d;
}
__device__ __forceinline__ u64 add2(u64 a, u64 b) {
    u64 d;
    asm("add.rn.f32x2 %0, %1, %2;" : "=l"(d) : "l"(a), "l"(b));
    return d;
}
__device__ __forceinline__ float sum2(u64 a) {
    float lo = __uint_as_float((unsigned)(a & 0xffffffffull));
    float hi = __uint_as_float((unsigned)(a >> 32));
    return lo + hi;
}
__device__ __forceinline__ u64 pack2(float lo, float hi) {
    u64 d;
    asm("mov.b64 %0, {%1, %2};" : "=l"(d) : "f"(lo), "f"(hi));
    return d;
}

// ---------------------------------------------------------------------------
// Fold Q into Wk (bias c[h] dropped: per-head constant is softmax-invariant).
// ---------------------------------------------------------------------------
__global__ void precompute_weff(const float* __restrict__ Q,
                                const float* __restrict__ Wk) {
    const float inv_temp = 0.35355339059327373f;  // 1/sqrt(8)
    int i = threadIdx.x;  // 0..255
#pragma unroll
    for (int h = 0; h < NHEAD; ++h) {
        float s = 0.f;
#pragma unroll
        for (int d = 0; d < 8; ++d)
            s += Q[h * 8 + d] * Wk[(h * 8 + d) * D_IN + i];
        g_weff[h * D_IN + i] = s * inv_temp;
    }
}

// ---------------------------------------------------------------------------
// PERSISTENT, DOUBLE-BUFFERED: 148 CTAs x 1024 threads (1/SM, 32 warps).
// Copy of batch i+1 overlaps the whole compute of batch i.
// Warp = (kh, hh, sg): 8 heads x half-row (R14 layout), sg in 0..7.
// ---------------------------------------------------------------------------
__global__ __launch_bounds__(1024, 1)
void fused_attn_kernel(const float* __restrict__ v_g,
                       const unsigned char* __restrict__ pad_mask,
                       float* __restrict__ out_g,    // [B, 256]
                       float* __restrict__ attn_g,   // [H, B, S]
                       int B) {
    extern __shared__ float v_buf[];                  // 2 x 15360 floats
    __shared__ float sc_part[2][NHEAD][SC_STRIDE];    // k-half partial scores
    __shared__ u64 part2[7][128];
    __shared__ __align__(8) u64 mbar[2];

    const int t = threadIdx.x;
    const int wid = t >> 5;        // 0..31
    const int lane = t & 31;
    const int stride = gridDim.x;

    const unsigned mb0 = (unsigned)__cvta_generic_to_shared(&mbar[0]);
    const unsigned mb1 = (unsigned)__cvta_generic_to_shared(&mbar[1]);
    const unsigned dst0 = (unsigned)__cvta_generic_to_shared(v_buf);
    const unsigned dst1 = (unsigned)__cvta_generic_to_shared(v_buf + V_FLOATS);

    if (t < 2)
        asm volatile("mbarrier.init.shared.b64 [%0], %1;"
                     :: "r"(t ? mb1 : mb0), "r"(1));
    __syncthreads();

    // first copy: batch blockIdx.x -> buffer 0
    if (t == 0) {
        asm volatile("mbarrier.arrive.expect_tx.shared.b64 _, [%0], %1;"
                     :: "r"(mb0), "r"(V_BYTES) : "memory");
        asm volatile(
            "cp.async.bulk.shared::cluster.global.mbarrier::complete_tx::bytes "
            "[%0], [%1], %2, [%3];"
            :: "r"(dst0), "l"(v_g + (size_t)blockIdx.x * V_FLOATS),
               "r"(V_BYTES), "r"(mb0) : "memory");
    }

    // ---- w preload once: 8 heads x k-half, PERMUTED j^e (sel-free tree) ----
    const int kh = wid & 1;        // k half
    const int hh = (wid >> 1) & 1; // head half
    const int sg = wid >> 2;       // s group: rows sg, sg+8, ...
    const int e = (lane >> 2) & 7; // lane-group head offset
    u64 wx[8], wy[8];
    {
        const float4* wg4 = (const float4*)g_weff;
#pragma unroll
        for (int j = 0; j < 8; ++j) {
            int h = hh * 8 + (j ^ e);
            float4 f = __ldg(wg4 + h * 64 + kh * 32 + lane);
            wx[j] = pack2(f.x, f.y);
            wy[j] = pack2(f.z, f.w);
        }
    }

    const bool store_lane = (lane & 3) == 0;
    float* dst_sc = &sc_part[kh][hh * 8 + e][0];

    int par0 = 0, par1 = 0;
    int i = 0;
    for (int b = blockIdx.x; b < B; b += stride, ++i) {
        const int bi = i & 1;
        const float* v_sm = v_buf + (size_t)bi * V_FLOATS;

        // prefetch batch b+stride into the OTHER buffer (free since the
        // end-of-previous-iteration barrier followed its last v read)
        if (t == 0 && b + stride < B) {
            const unsigned mbn = bi ? mb0 : mb1;
            const unsigned dstn = bi ? dst0 : dst1;
            asm volatile("mbarrier.arrive.expect_tx.shared.b64 _, [%0], %1;"
                         :: "r"(mbn), "r"(V_BYTES) : "memory");
            asm volatile(
                "cp.async.bulk.shared::cluster.global.mbarrier::complete_tx::bytes "
                "[%0], [%1], %2, [%3];"
                :: "r"(dstn), "l"(v_g + (size_t)(b + stride) * V_FLOATS),
                   "r"(V_BYTES), "r"(mbn) : "memory");
        }

        // wait for current buffer
        {
            const unsigned mbc = bi ? mb1 : mb0;
            const int par = bi ? par1 : par0;
            asm volatile(
                "{\n\t"
                ".reg .pred P;\n"
                "WAIT_%=:\n\t"
                "mbarrier.try_wait.parity.acquire.cta.shared::cta.b64 P, [%0], %1;\n\t"
                "@P bra DONE_%=;\n\t"
                "bra WAIT_%=;\n"
                "DONE_%=:\n\t"
                "}"
                :: "r"(mbc), "r"(par) : "memory");
            if (bi) par1 ^= 1; else par0 ^= 1;
        }

        // ---- Phase B: partial scores, 8 heads over this warp's k-half ----
        {
            const ulonglong2* vb = (const ulonglong2*)v_sm + kh * 32 + lane;
#pragma unroll 4
            for (int r = sg; r < S_LEN; r += 8) {   // 7 or 8 rows per warp
                ulonglong2 vv = vb[(size_t)r * 64];
                float p[8];
#pragma unroll
                for (int j = 0; j < 8; ++j) {
                    u64 a = mul2(vv.x, wx[j]);
                    a = fma2(vv.y, wy[j], a);
                    p[j] = sum2(a);
                }
                float q[4];
#pragma unroll
                for (int j = 0; j < 4; ++j)
                    q[j] = p[j] + __shfl_xor_sync(0xffffffffu, p[j + 4], 16);
                float r2[2];
#pragma unroll
                for (int j = 0; j < 2; ++j)
                    r2[j] = q[j] + __shfl_xor_sync(0xffffffffu, q[j + 2], 8);
                float s = r2[0] + __shfl_xor_sync(0xffffffffu, r2[1], 4);
                s += __shfl_xor_sync(0xffffffffu, s, 2);
                s += __shfl_xor_sync(0xffffffffu, s, 1);
                if (store_lane) dst_sc[r] = s;
            }
        }
        __syncthreads();

        // ---- Phase C: combine k-halves, masked softmax (warps 0..15) ----
        if (wid < NHEAD) {
            const unsigned char* pm = pad_mask + (size_t)b * S_LEN;
            const int h = wid;
            float x0 = sc_part[0][h][lane] + sc_part[1][h][lane];
            const bool has1 = (lane + 32) < S_LEN;
            float x1 = has1
                ? sc_part[0][h][lane + 32] + sc_part[1][h][lane + 32]
                : -1e30f;
            if (pm[lane]) x0 = -1e6f;
            if (has1 && pm[lane + 32]) x1 = -1e6f;

            float m = fmaxf(x0, x1);
#pragma unroll
            for (int o = 16; o > 0; o >>= 1)
                m = fmaxf(m, __shfl_xor_sync(0xffffffffu, m, o));

            float e0 = __expf(x0 - m);
            float e1 = has1 ? __expf(x1 - m) : 0.f;
            float ss = e0 + e1;
#pragma unroll
            for (int o = 16; o > 0; o >>= 1)
                ss += __shfl_xor_sync(0xffffffffu, ss, o);
            float inv = 1.0f / ss;

            float a0 = e0 * inv;
            float a1 = e1 * inv;
            sc_part[0][h][lane] = a0;
            if (has1) sc_part[0][h][lane + 32] = a1;

            float* ag = attn_g + ((size_t)h * B + b) * S_LEN;
            ag[lane] = a0;
            if (has1) ag[lane + 32] = a1;
        }
        __syncthreads();

        // ---- Phase D: out = attn @ v_heads, f32x2, 8-way s-split ----
        {
            const int cp = t & 127;     // column pair: cols 2cp, 2cp+1
            const int sh = t >> 7;      // s chunk: 0..7
            const int h = cp >> 3;
            const u64* vc = (const u64*)v_sm + cp;
            u64 acc = 0ull;
            const int s0 = (sh * 15) >> 1;
            const int s1 = ((sh + 1) * 15) >> 1;
#pragma unroll 4
            for (int s = s0; s < s1; ++s) {
                float a = sc_part[0][h][s];
                acc = fma2(vc[(size_t)s * 128], pack2(a, a), acc);
            }
            if (sh != 0) part2[sh - 1][cp] = acc;
            __syncthreads();
            if (sh == 0) {
#pragma unroll
                for (int j = 0; j < 7; ++j) acc = add2(acc, part2[j][cp]);
                ((u64*)(out_g + (size_t)b * D_IN))[cp] = acc;
            }
        }
        __syncthreads();   // v reads + sc_part/part2 done before next iter
    }
}

// ---------------------------------------------------------------------------
extern "C" void kernel_launch(void* const* d_in, const int* in_sizes, int n_in,
                              void* d_out, int out_size) {
    const float* v = (const float*)d_in[0];
    const float* Q = (const float*)d_in[1];
    const float* Wk = (const float*)d_in[2];
    const unsigned char* pm = (const unsigned char*)d_in[4];

    const int B = in_sizes[0] / V_FLOATS;

    float* out = (float*)d_out;                  // [B, 256]
    float* attn = out + (size_t)B * D_IN;        // [H, B, S]

    precompute_weff<<<1, 256>>>(Q, Wk);

    const size_t smem_bytes = 2 * (size_t)V_BYTES;   // double buffer
    cudaFuncSetAttribute(fused_attn_kernel,
                         cudaFuncAttributeMaxDynamicSharedMemorySize,
                         (int)smem_bytes);

    fused_attn_kernel<<<GRID_P, 1024, smem_bytes>>>(v, pm, out, attn, B);
}

// round 17
// speedup vs baseline: 1.1879x; 1.1879x over previous
#include <cuda_runtime.h>
#include <math.h>

#define S_LEN 60
#define D_IN  256
#define NHEAD 16
#define SC_STRIDE 68
#define V_FLOATS (S_LEN * D_IN)          // 15360
#define CHUNK_ROWS 15
#define CHUNK_FLOATS (CHUNK_ROWS * D_IN) // 3840
#define CHUNK_BYTES (CHUNK_FLOATS * 4)   // 15360

typedef unsigned long long u64;

__device__ __align__(16) float g_weff[NHEAD * D_IN];

__device__ __forceinline__ u64 fma2(u64 a, u64 b, u64 c) {
    u64 d;
    asm("fma.rn.f32x2 %0, %1, %2, %3;" : "=l"(d) : "l"(a), "l"(b), "l"(c));
    return d;
}
__device__ __forceinline__ u64 mul2(u64 a, u64 b) {
    u64 d;
    asm("mul.rn.f32x2 %0, %1, %2;" : "=l"(d) : "l"(a), "l"(b));
    return d;
}
__device__ __forceinline__ u64 add2(u64 a, u64 b) {
    u64 d;
    asm("add.rn.f32x2 %0, %1, %2;" : "=l"(d) : "l"(a), "l"(b));
    return d;
}
__device__ __forceinline__ float sum2(u64 a) {
    float lo = __uint_as_float((unsigned)(a & 0xffffffffull));
    float hi = __uint_as_float((unsigned)(a >> 32));
    return lo + hi;
}
__device__ __forceinline__ u64 pack2(float lo, float hi) {
    u64 d;
    asm("mov.b64 %0, {%1, %2};" : "=l"(d) : "f"(lo), "f"(hi));
    return d;
}

// ---------------------------------------------------------------------------
// Fold Q into Wk (bias c[h] dropped: per-head constant is softmax-invariant).
// ---------------------------------------------------------------------------
__global__ void precompute_weff(const float* __restrict__ Q,
                                const float* __restrict__ Wk) {
    const float inv_temp = 0.35355339059327373f;  // 1/sqrt(8)
    int i = threadIdx.x;  // 0..255
#pragma unroll
    for (int h = 0; h < NHEAD; ++h) {
        float s = 0.f;
#pragma unroll
        for (int d = 0; d < 8; ++d)
            s += Q[h * 8 + d] * Wk[(h * 8 + d) * D_IN + i];
        g_weff[h * D_IN + i] = s * inv_temp;
    }
}

// ---------------------------------------------------------------------------
// One 512-thread CTA per batch, 2 CTAs/SM.
// v arrives in 4 row-chunks (own mbarrier each); warp (kh,hh,sg) waits only
// for chunk sg, so compute starts before the full copy lands.
// ---------------------------------------------------------------------------
__global__ __launch_bounds__(512, 2)
void fused_attn_kernel(const float* __restrict__ v_g,
                       const unsigned char* __restrict__ pad_mask,
                       float* __restrict__ out_g,    // [B, 256]
                       float* __restrict__ attn_g,   // [H, B, S]
                       int B) {
    extern __shared__ float v_sm[];                   // 15360 floats
    __shared__ float sc_part[2][NHEAD][SC_STRIDE];    // k-half partial scores
    __shared__ u64 part2[3][128];
    __shared__ __align__(8) u64 mbar[4];

    const int t = threadIdx.x;
    const int b = blockIdx.x;
    const int wid = t >> 5;        // 0..15
    const int lane = t & 31;

    const unsigned mb_base = (unsigned)__cvta_generic_to_shared(&mbar[0]);
    const unsigned dst_base = (unsigned)__cvta_generic_to_shared(v_sm);

    // ---- init 4 mbarriers, then 4 chunked bulk copies ----
    if (t < 4)
        asm volatile("mbarrier.init.shared.b64 [%0], %1;"
                     :: "r"(mb_base + t * 8), "r"(1));
    __syncthreads();
    if (t == 0) {
        const float* src = v_g + (size_t)b * V_FLOATS;
#pragma unroll
        for (int c = 0; c < 4; ++c) {
            const unsigned mbc = mb_base + c * 8;
            asm volatile("mbarrier.arrive.expect_tx.shared.b64 _, [%0], %1;"
                         :: "r"(mbc), "r"(CHUNK_BYTES) : "memory");
            asm volatile(
                "cp.async.bulk.shared::cluster.global.mbarrier::complete_tx::bytes "
                "[%0], [%1], %2, [%3];"
                :: "r"(dst_base + c * CHUNK_BYTES),
                   "l"(src + (size_t)c * CHUNK_FLOATS),
                   "r"(CHUNK_BYTES), "r"(mbc) : "memory");
        }
    }

    // ---- w preload (overlaps copies): 8 heads x k-half, PERMUTED j^e ----
    const int kh = wid & 1;        // k half
    const int hh = (wid >> 1) & 1; // head half
    const int sg = wid >> 2;       // row chunk: rows [sg*15, sg*15+15)
    const int e = (lane >> 2) & 7; // lane-group head offset
    u64 wx[8], wy[8];
    {
        const float4* wg4 = (const float4*)g_weff;
#pragma unroll
        for (int j = 0; j < 8; ++j) {
            int h = hh * 8 + (j ^ e);
            float4 f = __ldg(wg4 + h * 64 + kh * 32 + lane);
            wx[j] = pack2(f.x, f.y);
            wy[j] = pack2(f.z, f.w);
        }
    }

    // ---- wait ONLY for this warp's chunk ----
    {
        const unsigned mbc = mb_base + sg * 8;
        asm volatile(
            "{\n\t"
            ".reg .pred P;\n"
            "WAIT_%=:\n\t"
            "mbarrier.try_wait.parity.acquire.cta.shared::cta.b64 P, [%0], 0;\n\t"
            "@P bra DONE_%=;\n\t"
            "bra WAIT_%=;\n"
            "DONE_%=:\n\t"
            "}"
            :: "r"(mbc) : "memory");
    }

    // ---- Phase B: partial scores, 8 heads over this warp's k-half ----
    {
        const bool store_lane = (lane & 3) == 0;
        float* dst_sc = &sc_part[kh][hh * 8 + e][0];
        const ulonglong2* vb = (const ulonglong2*)v_sm + kh * 32 + lane;
        const int r0 = sg * CHUNK_ROWS;

#pragma unroll 5
        for (int r = r0; r < r0 + CHUNK_ROWS; ++r) {   // 15 contiguous rows
            ulonglong2 vv = vb[(size_t)r * 64];
            float p[8];
#pragma unroll
            for (int j = 0; j < 8; ++j) {
                u64 a = mul2(vv.x, wx[j]);
                a = fma2(vv.y, wy[j], a);
                p[j] = sum2(a);
            }
            // sel-free permuted tree: xor16 (4 shfl), xor8 (2), xor4 (1)
            float q[4];
#pragma unroll
            for (int j = 0; j < 4; ++j)
                q[j] = p[j] + __shfl_xor_sync(0xffffffffu, p[j + 4], 16);
            float r2[2];
#pragma unroll
            for (int j = 0; j < 2; ++j)
                r2[j] = q[j] + __shfl_xor_sync(0xffffffffu, q[j + 2], 8);
            float s = r2[0] + __shfl_xor_sync(0xffffffffu, r2[1], 4);
            s += __shfl_xor_sync(0xffffffffu, s, 2);
            s += __shfl_xor_sync(0xffffffffu, s, 1);
            if (store_lane) dst_sc[r] = s;
        }
    }
    __syncthreads();   // all chunks arrived + all partial scores written

    // ---- Phase C: combine k-halves, masked softmax (1 head/warp) ----
    {
        const unsigned char* pm = pad_mask + (size_t)b * S_LEN;
        const int h = wid;
        float x0 = sc_part[0][h][lane] + sc_part[1][h][lane];
        const bool has1 = (lane + 32) < S_LEN;
        float x1 = has1
            ? sc_part[0][h][lane + 32] + sc_part[1][h][lane + 32]
            : -1e30f;
        if (pm[lane]) x0 = -1e6f;
        if (has1 && pm[lane + 32]) x1 = -1e6f;

        float m = fmaxf(x0, x1);
#pragma unroll
        for (int o = 16; o > 0; o >>= 1)
            m = fmaxf(m, __shfl_xor_sync(0xffffffffu, m, o));

        float e0 = __expf(x0 - m);
        float e1 = has1 ? __expf(x1 - m) : 0.f;
        float ss = e0 + e1;
#pragma unroll
        for (int o = 16; o > 0; o >>= 1)
            ss += __shfl_xor_sync(0xffffffffu, ss, o);
        float inv = 1.0f / ss;

        float a0 = e0 * inv;
        float a1 = e1 * inv;
        sc_part[0][h][lane] = a0;
        if (has1) sc_part[0][h][lane + 32] = a1;

        float* ag = attn_g + ((size_t)h * B + b) * S_LEN;
        ag[lane] = a0;
        if (has1) ag[lane + 32] = a1;
    }
    __syncthreads();

    // ---- Phase D: out = attn @ v_heads, f32x2, 4-way s-split ----
    {
        const int cp = t & 127;     // column pair: cols 2cp, 2cp+1
        const int sh = t >> 7;      // s quarter: 0..3, 15 s each
        const int h = cp >> 3;      // 8 col-pairs per head
        const u64* vc = (const u64*)v_sm + cp;   // row stride 128 u64
        u64 acc = 0ull;
        const int s0 = sh * 15;
#pragma unroll 5
        for (int s = s0; s < s0 + 15; ++s) {
            float a = sc_part[0][h][s];
            acc = fma2(vc[(size_t)s * 128], pack2(a, a), acc);
        }
        if (sh != 0) part2[sh - 1][cp] = acc;
        __syncthreads();
        if (sh == 0) {
            acc = add2(acc, part2[0][cp]);
            acc = add2(acc, add2(part2[1][cp], part2[2][cp]));
            ((u64*)(out_g + (size_t)b * D_IN))[cp] = acc;
        }
    }
}

// ---------------------------------------------------------------------------
extern "C" void kernel_launch(void* const* d_in, const int* in_sizes, int n_in,
                              void* d_out, int out_size) {
    const float* v = (const float*)d_in[0];
    const float* Q = (const float*)d_in[1];
    const float* Wk = (const float*)d_in[2];
    const unsigned char* pm = (const unsigned char*)d_in[4];

    const int B = in_sizes[0] / V_FLOATS;

    float* out = (float*)d_out;                  // [B, 256]
    float* attn = out + (size_t)B * D_IN;        // [H, B, S]

    precompute_weff<<<1, 256>>>(Q, Wk);

    const size_t smem_bytes = (size_t)V_FLOATS * 4;
    cudaFuncSetAttribute(fused_attn_kernel,
                         cudaFuncAttributeMaxDynamicSharedMemorySize,
                         (int)smem_bytes);

    fused_attn_kernel<<<B, 512, smem_bytes>>>(v, pm, out, attn, B);
}